// round 1
// baseline (speedup 1.0000x reference)
#include <cuda_runtime.h>
#include <math.h>

// Problem shapes (fixed): x (4,1,512,180) float32 -> out (4,1,512,512) float32
#define NB   4
#define H    512       // rows of sinogram = W (output side)
#define WIN  180       // angle columns in sinogram
#define L    180       // number of angles
#define W    512       // output width/height

#define PSTRIDE 516    // float2 stride per (n,l) pair array (514 used, padded)

// Scratch: per (n,l) padded blended column as (P[k], P[k+1]-P[k]) pairs.
// base index b+1 in [0,513]; pair[513] = (0,0).
__device__ static float2 g_pairs[NB * L * PSTRIDE];

// ---------------------------------------------------------------------------
// Prep: blend the two sinogram columns selected by gx for each angle, build
// padded pair table. Exactly replicates reference fp32 index arithmetic.
// ---------------------------------------------------------------------------
__global__ void irad_prep(const float* __restrict__ x) {
    const int l = blockIdx.x;
    const int n = blockIdx.y;
    __shared__ float col[H];

    // Xc = linspace(-1,1,L)[l] = -1 + l * (2/(L-1))  (fp32, matching jnp)
    float Xc  = fmaf((float)l, 2.0f / 179.0f, -1.0f);
    float ix  = (Xc + 1.0f) * 0.5f * 179.0f;
    float i0f = floorf(ix);
    float wx1 = ix - i0f;
    float wx0 = 1.0f - wx1;
    int   i0  = (int)i0f;
    int   i1  = i0 + 1;
    bool  v0  = (i0 >= 0) && (i0 <= WIN - 1);
    bool  v1  = (i1 >= 0) && (i1 <= WIN - 1);

    const float* xn = x + (size_t)n * H * WIN;
    for (int r = threadIdx.x; r < H; r += blockDim.x) {
        float a = v0 ? xn[r * WIN + i0] : 0.0f;
        float b = v1 ? xn[r * WIN + i1] : 0.0f;
        col[r] = wx0 * a + wx1 * b;
    }
    __syncthreads();

    float2* pr = g_pairs + (size_t)(n * L + l) * PSTRIDE;
    for (int k = threadIdx.x; k <= 513; k += blockDim.x) {
        float P  = (k >= 1 && k <= 512) ? col[k - 1] : 0.0f;  // P[k]
        float Pn = (k <= 511) ? col[k] : 0.0f;                // P[k+1]
        pr[k] = make_float2(P, Pn - P);
    }
}

// ---------------------------------------------------------------------------
// Main: 64x64 output tile per block, 256 threads x 16 pixels. Angles staged
// in chunks of CH; per angle only the tile's iy-window is loaded into smem.
// ---------------------------------------------------------------------------
#define TILE 64
#define CH   45     // angles per smem chunk (180 = 4 * 45)
#define WMAX 96     // max window entries per angle (<= 94 needed)

__global__ void __launch_bounds__(256) irad_main(float* __restrict__ out) {
    __shared__ float2 sP[CH * WMAX];
    __shared__ float  sCa[CH];
    __shared__ float  sNsa[CH];
    __shared__ int    sAb[CH];   // smem base (float2 units) - ws + 1

    const int n   = blockIdx.z;
    const int j0  = blockIdx.x * TILE;
    const int i0t = blockIdx.y * TILE;
    const int t   = threadIdx.x;
    const int jl  = t & 63;
    const int r0  = t >> 6;          // 0..3
    const int j   = j0 + jl;
    const int wid  = t >> 5;
    const int lane = t & 31;

    const float uj = fmaf((float)j, 2.0f / 511.0f, -1.0f);

    float ui[16];
    float acc[16];
#pragma unroll
    for (int k = 0; k < 16; k++) {
        ui[k]  = fmaf((float)(i0t + r0 + 4 * k), 2.0f / 511.0f, -1.0f);
        acc[k] = 0.0f;
    }

    // Tile corner u-values for window bounds
    const float uj0 = fmaf((float)j0,            2.0f / 511.0f, -1.0f);
    const float uj1 = fmaf((float)(j0 + TILE-1), 2.0f / 511.0f, -1.0f);
    const float vi0 = fmaf((float)i0t,            2.0f / 511.0f, -1.0f);
    const float vi1 = fmaf((float)(i0t + TILE-1), 2.0f / 511.0f, -1.0f);

    const float2* gp = g_pairs + (size_t)n * L * PSTRIDE;

    for (int c0 = 0; c0 < L; c0 += CH) {
        // ---- stage phase: each warp handles angles lc = wid, wid+8, ... ----
        for (int lc = wid; lc < CH; lc += 8) {
            const int l = c0 + lc;
            float rad = (float)l * (3.14159265358979323846f / 180.0f);
            float cs, sn;
            __sincosf(rad, &sn, &cs);
            // use accurate versions to match fp32 reference closely
            cs = cosf(rad);
            sn = sinf(rad);
            float ca = cs * 255.5f;
            float sa = sn * 255.5f;

            float jlo = fminf(ca * uj0, ca * uj1);
            float jhi = fmaxf(ca * uj0, ca * uj1);
            float ilo = fminf(sa * vi0, sa * vi1);
            float ihi = fmaxf(sa * vi0, sa * vi1);
            float iymin = 255.5f + jlo - ihi;
            float iymax = 255.5f + jhi - ilo;
            // same clamp as per-pixel path for consistency
            iymin = fminf(fmaxf(iymin, -1.0f), 512.5f);
            iymax = fminf(fmaxf(iymax, -1.0f), 512.5f);

            int ws = (int)floorf(iymin);        // base_min - 1 (guard)
            int we = (int)floorf(iymax) + 2;    // base_max + 1 (guard)
            ws = min(max(ws, 0), 513);
            we = min(max(we, 0), 513);
            int cnt = we - ws + 1;              // <= 94 <= WMAX

            const float2* src = gp + (size_t)l * PSTRIDE + ws;
            float2* dst = sP + lc * WMAX;
            for (int e = lane; e < cnt; e += 32) dst[e] = src[e];
            if (lane == 0) {
                sCa[lc]  = ca;
                sNsa[lc] = -sa;
                sAb[lc]  = lc * WMAX - ws + 1;  // + 1 for base = b+1
            }
        }
        __syncthreads();

        // ---- compute phase ----
        for (int lc = 0; lc < CH; lc++) {
            const float ca  = sCa[lc];
            const float nsa = sNsa[lc];
            const int   ab  = sAb[lc];
            const float t0  = fmaf(ca, uj, 255.5f);
#pragma unroll
            for (int k = 0; k < 16; k++) {
                float iy = fmaf(nsa, ui[k], t0);
                iy = fmaxf(iy, -1.0f);
                iy = fminf(iy, 512.5f);
                int   b = __float2int_rd(iy);
                float f = (float)b;
                float w = iy - f;
                float2 p = sP[ab + b];
                acc[k] = fmaf(w, p.y, acc[k] + p.x);
            }
        }
        __syncthreads();
    }

    const float scale = (float)(M_PI / 360.0);   // pi / (2*L)
    float* po = out + ((size_t)(n * W + i0t + r0) * W) + j;
#pragma unroll
    for (int k = 0; k < 16; k++) {
        po[(size_t)(4 * k) * W] = acc[k] * scale;
    }
}

// ---------------------------------------------------------------------------
extern "C" void kernel_launch(void* const* d_in, const int* in_sizes, int n_in,
                              void* d_out, int out_size) {
    const float* x = (const float*)d_in[0];
    float* out = (float*)d_out;
    (void)in_sizes; (void)n_in; (void)out_size;

    irad_prep<<<dim3(L, NB), 128>>>(x);
    irad_main<<<dim3(W / TILE, W / TILE, NB), 256>>>(out);
}

// round 2
// speedup vs baseline: 1.1948x; 1.1948x over previous
#include <cuda_runtime.h>
#include <math.h>

// Problem shapes (fixed): x (4,1,512,180) float32 -> out (4,1,512,512) float32
#define NB   4
#define H    512       // rows of sinogram
#define WIN  180       // angle columns in sinogram
#define L    180       // number of angles
#define W    512       // output width/height

// Padded pair table: index k = (b+1) + PAD, b = floor(iy), iy in [-105.8, 616.8]
// -> k in [7, 731). PSTRIDE2 = 744 covers it; zeros outside the valid core.
#define PAD      112
#define PSTRIDE2 744

__device__ static float2 g_pairs[NB * L * PSTRIDE2];
__device__ static float2 g_trig[L];   // (ca, sa) = 255.5*(cos, sin)

// ---------------------------------------------------------------------------
// Prep: per (n,l) blend the two sinogram columns selected by gx (fp32 math
// replicating the reference), then emit padded (P[k], P[k+1]-P[k]) pairs.
// ---------------------------------------------------------------------------
__global__ void irad_prep(const float* __restrict__ x) {
    const int l = blockIdx.x;
    const int n = blockIdx.y;
    __shared__ float col[H];

    float Xc  = fmaf((float)l, 2.0f / 179.0f, -1.0f);
    float ix  = (Xc + 1.0f) * 0.5f * 179.0f;
    float i0f = floorf(ix);
    float wx1 = ix - i0f;
    float wx0 = 1.0f - wx1;
    int   i0  = (int)i0f;
    int   i1  = i0 + 1;
    bool  v0  = (i0 >= 0) && (i0 <= WIN - 1);
    bool  v1  = (i1 >= 0) && (i1 <= WIN - 1);

    const float* xn = x + (size_t)n * H * WIN;
    for (int r = threadIdx.x; r < H; r += blockDim.x) {
        float a = v0 ? xn[r * WIN + i0] : 0.0f;
        float b = v1 ? xn[r * WIN + i1] : 0.0f;
        col[r] = wx0 * a + wx1 * b;
    }
    if (threadIdx.x == 0 && n == 0) {
        float rad = (float)l * (3.14159265358979323846f / 180.0f);
        g_trig[l] = make_float2(cosf(rad) * 255.5f, sinf(rad) * 255.5f);
    }
    __syncthreads();

    float2* pr = g_pairs + (size_t)(n * L + l) * PSTRIDE2;
    for (int k = threadIdx.x; k < PSTRIDE2; k += blockDim.x) {
        int kk = k - PAD;                                    // = b+1
        float P  = (kk >= 1 && kk <= 512) ? col[kk - 1] : 0.0f;
        float Pn = (kk >= 0 && kk <= 511) ? col[kk]     : 0.0f;
        pr[k] = make_float2(P, Pn - P);
    }
}

// ---------------------------------------------------------------------------
// Main: 32x32 output tile, 256 threads, 4 px/thread. Angles staged in chunks;
// per angle only the tile's iy-window (<=47 entries) is copied to smem.
// No clamps: padded table absorbs out-of-range samples as exact zeros.
// ---------------------------------------------------------------------------
#define TJ   32
#define TI   32
#define CH   45     // angles per chunk (180 = 4*45)
#define WMAX 48     // 31*(|c|+|s|) + 4 <= 47.9

__global__ void __launch_bounds__(256) irad_main(float* __restrict__ out) {
    __shared__ float2 sP[CH * WMAX];
    __shared__ float4 sMeta[CH];       // (ca, -sa, as_float(ab), unused)

    const int n    = blockIdx.z;
    const int j0   = blockIdx.x * TJ;
    const int i0t  = blockIdx.y * TI;
    const int t    = threadIdx.x;
    const int lane = t & 31;           // jl within tile row
    const int wid  = t >> 5;           // 0..7, also row group
    const int j    = j0 + lane;

    const float uj = fmaf((float)j, 2.0f / 511.0f, -1.0f);

    float ui[4], acc[4];
#pragma unroll
    for (int k = 0; k < 4; k++) {
        ui[k]  = fmaf((float)(i0t + wid + 8 * k), 2.0f / 511.0f, -1.0f);
        acc[k] = 0.0f;
    }

    // tile corner u-values for window bounds
    const float uj0 = fmaf((float)j0,           2.0f / 511.0f, -1.0f);
    const float uj1 = fmaf((float)(j0 + TJ-1),  2.0f / 511.0f, -1.0f);
    const float vi0 = fmaf((float)i0t,          2.0f / 511.0f, -1.0f);
    const float vi1 = fmaf((float)(i0t + TI-1), 2.0f / 511.0f, -1.0f);

    const float2* gp = g_pairs + (size_t)n * L * PSTRIDE2;

    for (int c0 = 0; c0 < L; c0 += CH) {
        // ---- stage: warp w handles angles lc = w, w+8, ... ----
        for (int lc = wid; lc < CH; lc += 8) {
            const int l = c0 + lc;
            float2 tr = g_trig[l];
            float ca = tr.x, sa = tr.y;

            float jlo = fminf(ca * uj0, ca * uj1);
            float jhi = fmaxf(ca * uj0, ca * uj1);
            float ilo = fminf(sa * vi0, sa * vi1);
            float ihi = fmaxf(sa * vi0, sa * vi1);
            float iymin = 255.5f + jlo - ihi;
            float iymax = 255.5f + jhi - ilo;

            int ws  = (int)floorf(iymin);
            int we  = (int)floorf(iymax) + 2;
            int cnt = we - ws + 1;                 // <= 47

            const float2* src = gp + (size_t)l * PSTRIDE2 + (ws + PAD);
            float2* dst = sP + lc * WMAX;
            for (int e = lane; e < cnt; e += 32) dst[e] = src[e];
            if (lane == 0) {
                int ab = lc * WMAX - ws + 1;       // smem entry = ab + b
                sMeta[lc] = make_float4(ca, -sa, __int_as_float(ab), 0.0f);
            }
        }
        __syncthreads();

        // ---- compute ----
        for (int lc = 0; lc < CH; lc++) {
            const float4 m  = sMeta[lc];
            const float2* pa = sP + __float_as_int(m.z);
            const float t0  = fmaf(m.x, uj, 255.5f);
#pragma unroll
            for (int k = 0; k < 4; k++) {
                float iy = fmaf(m.y, ui[k], t0);
                int   b  = __float2int_rd(iy);
                float w  = iy - (float)b;
                float2 p = pa[b];
                acc[k] = fmaf(w, p.y, acc[k] + p.x);
            }
        }
        __syncthreads();
    }

    const float scale = (float)(M_PI / 360.0);   // pi / (2*L)
    float* po = out + ((size_t)(n * W + i0t + wid) * W) + j;
#pragma unroll
    for (int k = 0; k < 4; k++) {
        po[(size_t)(8 * k) * W] = acc[k] * scale;
    }
}

// ---------------------------------------------------------------------------
extern "C" void kernel_launch(void* const* d_in, const int* in_sizes, int n_in,
                              void* d_out, int out_size) {
    const float* x = (const float*)d_in[0];
    float* out = (float*)d_out;
    (void)in_sizes; (void)n_in; (void)out_size;

    irad_prep<<<dim3(L, NB), 128>>>(x);
    irad_main<<<dim3(W / TJ, W / TI, NB), 256>>>(out);
}

// round 3
// speedup vs baseline: 1.2909x; 1.0805x over previous
#include <cuda_runtime.h>
#include <math.h>

// Problem shapes (fixed): x (4,1,512,180) float32 -> out (4,1,512,512) float32
#define NB   4
#define H    512
#define WIN  180
#define L    180
#define W    512

// Padded pair table: index k = (b+1) + PAD, zeros outside valid core.
#define PAD      112
#define PSTRIDE2 744

__device__ static float2 g_pairs[NB * L * PSTRIDE2];
__device__ static float2 g_trig[L];   // (ca, sa) = 255.5*(cos, sin)

// ---------------------------------------------------------------------------
// Prep: per (n,l) blend the two sinogram columns selected by gx (fp32 math
// replicating the reference), then emit padded (P[k], P[k+1]-P[k]) pairs.
// ---------------------------------------------------------------------------
__global__ void irad_prep(const float* __restrict__ x) {
    const int l = blockIdx.x;
    const int n = blockIdx.y;
    __shared__ float col[H];

    float Xc  = fmaf((float)l, 2.0f / 179.0f, -1.0f);
    float ix  = (Xc + 1.0f) * 0.5f * 179.0f;
    float i0f = floorf(ix);
    float wx1 = ix - i0f;
    float wx0 = 1.0f - wx1;
    int   i0  = (int)i0f;
    int   i1  = i0 + 1;
    bool  v0  = (i0 >= 0) && (i0 <= WIN - 1);
    bool  v1  = (i1 >= 0) && (i1 <= WIN - 1);

    const float* xn = x + (size_t)n * H * WIN;
    for (int r = threadIdx.x; r < H; r += blockDim.x) {
        float a = v0 ? xn[r * WIN + i0] : 0.0f;
        float b = v1 ? xn[r * WIN + i1] : 0.0f;
        col[r] = wx0 * a + wx1 * b;
    }
    if (threadIdx.x == 0 && n == 0) {
        float rad = (float)l * (3.14159265358979323846f / 180.0f);
        g_trig[l] = make_float2(cosf(rad) * 255.5f, sinf(rad) * 255.5f);
    }
    __syncthreads();

    float2* pr = g_pairs + (size_t)(n * L + l) * PSTRIDE2;
    for (int k = threadIdx.x; k < PSTRIDE2; k += blockDim.x) {
        int kk = k - PAD;                                    // = b+1
        float P  = (kk >= 1 && kk <= 512) ? col[kk - 1] : 0.0f;
        float Pn = (kk >= 0 && kk <= 511) ? col[kk]     : 0.0f;
        pr[k] = make_float2(P, Pn - P);
    }
}

// ---------------------------------------------------------------------------
// Main: 32x32 tile, 256 threads, 4 px/thread. Stage rescales each window
// entry e to (v0 - e*dv, dv) so the inner loop needs no fractional-weight
// computation: sample = q.x + iy' * q.y with e = floor(iy').
// ---------------------------------------------------------------------------
#define TJ   32
#define TI   32
#define CH   45
#define WMAX 48

__global__ void __launch_bounds__(256) irad_main(float* __restrict__ out) {
    __shared__ float2 sP[CH * WMAX];
    __shared__ float4 sMeta[CH];       // (ca, -sa, unused, 256.5 - ws)

    const int n    = blockIdx.z;
    const int j0   = blockIdx.x * TJ;
    const int i0t  = blockIdx.y * TI;
    const int t    = threadIdx.x;
    const int lane = t & 31;
    const int wid  = t >> 5;
    const int j    = j0 + lane;

    const float uj = fmaf((float)j, 2.0f / 511.0f, -1.0f);

    float ui[4], acc[4];
#pragma unroll
    for (int k = 0; k < 4; k++) {
        ui[k]  = fmaf((float)(i0t + wid + 8 * k), 2.0f / 511.0f, -1.0f);
        acc[k] = 0.0f;
    }

    const float uj0 = fmaf((float)j0,           2.0f / 511.0f, -1.0f);
    const float uj1 = fmaf((float)(j0 + TJ-1),  2.0f / 511.0f, -1.0f);
    const float vi0 = fmaf((float)i0t,          2.0f / 511.0f, -1.0f);
    const float vi1 = fmaf((float)(i0t + TI-1), 2.0f / 511.0f, -1.0f);

    const float2* gp = g_pairs + (size_t)n * L * PSTRIDE2;

    for (int c0 = 0; c0 < L; c0 += CH) {
        // ---- stage: warp w handles angles lc = w, w+8, ... ----
        for (int lc = wid; lc < CH; lc += 8) {
            const int l = c0 + lc;
            float2 tr = g_trig[l];
            float ca = tr.x, sa = tr.y;

            float jlo = fminf(ca * uj0, ca * uj1);
            float jhi = fmaxf(ca * uj0, ca * uj1);
            float ilo = fminf(sa * vi0, sa * vi1);
            float ihi = fmaxf(sa * vi0, sa * vi1);
            float iymin = 255.5f + jlo - ihi;
            float iymax = 255.5f + jhi - ilo;

            int ws  = (int)floorf(iymin);
            int we  = (int)floorf(iymax) + 2;
            int cnt = we - ws + 1;                 // <= 47

            const float2* src = gp + (size_t)l * PSTRIDE2 + (ws + PAD);
            float2* dst = sP + lc * WMAX;
            for (int e = lane; e < cnt; e += 32) {
                float2 p = src[e];
                // rescale: q.x = v0 - e*dv, so sample = q.x + iy' * dv
                dst[e] = make_float2(fmaf(-(float)e, p.y, p.x), p.y);
            }
            if (lane == 0) {
                // iy' = iy - ws + 1 ; t0' = 255.5 + 1 - ws + ca*uj
                sMeta[lc] = make_float4(ca, -sa, 0.0f, 256.5f - (float)ws);
            }
        }
        __syncthreads();

        // ---- compute: 6 issue slots per sample ----
        for (int lc = 0; lc < CH; lc++) {
            const float4 m   = sMeta[lc];
            const float2* pa = sP + lc * WMAX;
            const float t0   = fmaf(m.x, uj, m.w);
#pragma unroll
            for (int k = 0; k < 4; k++) {
                float iy = fmaf(m.y, ui[k], t0);
                int   e  = __float2int_rd(iy);
                float2 q = pa[e];
                acc[k] = fmaf(iy, q.y, acc[k] + q.x);
            }
        }
        __syncthreads();
    }

    const float scale = (float)(M_PI / 360.0);   // pi / (2*L)
    float* po = out + ((size_t)(n * W + i0t + wid) * W) + j;
#pragma unroll
    for (int k = 0; k < 4; k++) {
        po[(size_t)(8 * k) * W] = acc[k] * scale;
    }
}

// ---------------------------------------------------------------------------
extern "C" void kernel_launch(void* const* d_in, const int* in_sizes, int n_in,
                              void* d_out, int out_size) {
    const float* x = (const float*)d_in[0];
    float* out = (float*)d_out;
    (void)in_sizes; (void)n_in; (void)out_size;

    irad_prep<<<dim3(L, NB), 128>>>(x);
    irad_main<<<dim3(W / TJ, W / TI, NB), 256>>>(out);
}

// round 4
// speedup vs baseline: 1.3712x; 1.0622x over previous
#include <cuda_runtime.h>
#include <math.h>

// Problem shapes (fixed): x (4,1,512,180) float32 -> out (4,1,512,512) float32
#define NB   4
#define H    512
#define WIN  180
#define L    180
#define W    512

// Padded pair table: index k = (b+1) + PAD, zeros outside valid core.
// Entries pre-rescaled: (P[b] - b*dP, dP) so sample = q.x + iy*q.y (iy global).
#define PAD      112
#define PSTRIDE2 744

__device__ static float2 g_pairs[NB * L * PSTRIDE2];
__device__ static float2 g_trig[L];   // (ca, sa) = 255.5*(cos, sin)

// ---------------------------------------------------------------------------
// Prep: per (n,l) blend the two sinogram columns selected by gx (fp32 math
// replicating the reference), then emit globally-rescaled pairs.
// ---------------------------------------------------------------------------
__global__ void irad_prep(const float* __restrict__ x) {
    const int l = blockIdx.x;
    const int n = blockIdx.y;
    __shared__ float col[H];

    float Xc  = fmaf((float)l, 2.0f / 179.0f, -1.0f);
    float ix  = (Xc + 1.0f) * 0.5f * 179.0f;
    float i0f = floorf(ix);
    float wx1 = ix - i0f;
    float wx0 = 1.0f - wx1;
    int   i0  = (int)i0f;
    int   i1  = i0 + 1;
    bool  v0  = (i0 >= 0) && (i0 <= WIN - 1);
    bool  v1  = (i1 >= 0) && (i1 <= WIN - 1);

    const float* xn = x + (size_t)n * H * WIN;
    for (int r = threadIdx.x; r < H; r += blockDim.x) {
        float a = v0 ? xn[r * WIN + i0] : 0.0f;
        float b = v1 ? xn[r * WIN + i1] : 0.0f;
        col[r] = wx0 * a + wx1 * b;
    }
    if (threadIdx.x == 0 && n == 0) {
        float rad = (float)l * (3.14159265358979323846f / 180.0f);
        g_trig[l] = make_float2(cosf(rad) * 255.5f, sinf(rad) * 255.5f);
    }
    __syncthreads();

    float2* pr = g_pairs + (size_t)(n * L + l) * PSTRIDE2;
    for (int k = threadIdx.x; k < PSTRIDE2; k += blockDim.x) {
        int kk = k - PAD;                                    // = b+1
        float P  = (kk >= 1 && kk <= 512) ? col[kk - 1] : 0.0f;
        float Pn = (kk >= 0 && kk <= 511) ? col[kk]     : 0.0f;
        float d  = Pn - P;
        // global rescale: value(iy) = q.x + iy*q.y for floor(iy) = kk-1
        pr[k] = make_float2(fmaf(-(float)(kk - 1), d, P), d);
    }
}

// ---------------------------------------------------------------------------
// Main: 32x32 tile, 256 threads, 4 px/thread. Double-buffered angle chunks;
// next chunk's windows prefetched with cp.async while computing the current.
// ---------------------------------------------------------------------------
#define TJ   32
#define TI   32
#define CH   30     // angles per chunk (180 = 6*30)
#define NCH  (L / CH)
#define WMAX 48

__device__ __forceinline__ void cp_async8(unsigned dst, const void* src) {
    asm volatile("cp.async.ca.shared.global [%0], [%1], 8;\n"
                 :: "r"(dst), "l"(src));
}
__device__ __forceinline__ void cp_async_commit() {
    asm volatile("cp.async.commit_group;\n");
}
__device__ __forceinline__ void cp_async_wait_all() {
    asm volatile("cp.async.wait_group 0;\n");
}

__global__ void __launch_bounds__(256) irad_main(float* __restrict__ out) {
    __shared__ float2 sP[2 * CH * WMAX];
    __shared__ float4 sMeta[2 * CH];   // (ca, -sa, as_float(ab), unused)

    const int n    = blockIdx.z;
    const int j0   = blockIdx.x * TJ;
    const int i0t  = blockIdx.y * TI;
    const int t    = threadIdx.x;
    const int lane = t & 31;
    const int wid  = t >> 5;
    const int j    = j0 + lane;

    const float uj = fmaf((float)j, 2.0f / 511.0f, -1.0f);

    float ui[4], acc[4];
#pragma unroll
    for (int k = 0; k < 4; k++) {
        ui[k]  = fmaf((float)(i0t + wid + 8 * k), 2.0f / 511.0f, -1.0f);
        acc[k] = 0.0f;
    }

    const float uj0 = fmaf((float)j0,           2.0f / 511.0f, -1.0f);
    const float uj1 = fmaf((float)(j0 + TJ-1),  2.0f / 511.0f, -1.0f);
    const float vi0 = fmaf((float)i0t,          2.0f / 511.0f, -1.0f);
    const float vi1 = fmaf((float)(i0t + TI-1), 2.0f / 511.0f, -1.0f);

    const float2* gp = g_pairs + (size_t)n * L * PSTRIDE2;
    const unsigned sPb = (unsigned)__cvta_generic_to_shared(sP);

    // ---- stage(chunk c into buffer b): pure cp.async copies + meta ----
    auto stage = [&](int c, int b) {
        const int c0 = c * CH;
        const int bofs = b * CH;
        for (int lc = wid; lc < CH; lc += 8) {
            const int l = c0 + lc;
            float2 tr = g_trig[l];
            float ca = tr.x, sa = tr.y;

            float jlo = fminf(ca * uj0, ca * uj1);
            float jhi = fmaxf(ca * uj0, ca * uj1);
            float ilo = fminf(sa * vi0, sa * vi1);
            float ihi = fmaxf(sa * vi0, sa * vi1);
            float iymin = 255.5f + jlo - ihi;
            float iymax = 255.5f + jhi - ilo;

            int ws  = (int)floorf(iymin);
            int cnt = (int)floorf(iymax) + 3 - ws;           // <= 47

            const float2* src = gp + (size_t)l * PSTRIDE2 + (ws + PAD);
            unsigned dst = sPb + (unsigned)((bofs + lc) * WMAX) * 8u;
            for (int e = lane; e < cnt; e += 32)
                cp_async8(dst + (unsigned)e * 8u, src + e);
            if (lane == 0) {
                int ab = (bofs + lc) * WMAX + 1 - ws;        // smem idx = ab + floor(iy)
                sMeta[bofs + lc] = make_float4(ca, -sa, __int_as_float(ab), 0.0f);
            }
        }
        cp_async_commit();
    };

    stage(0, 0);

    for (int c = 0; c < NCH; c++) {
        const int b = c & 1;
        cp_async_wait_all();
        __syncthreads();                       // buf b ready; buf b^1 free

        if (c + 1 < NCH) stage(c + 1, b ^ 1);  // issue-only prefetch

        const float4* mp = sMeta + b * CH;
        for (int lc = 0; lc < CH; lc++) {
            const float4 m   = mp[lc];
            const float2* pa = sP + __float_as_int(m.z);
            const float t0   = fmaf(m.x, uj, 255.5f);
#pragma unroll
            for (int k = 0; k < 4; k++) {
                float iy = fmaf(m.y, ui[k], t0);
                int   e  = __float2int_rd(iy);
                float2 q = pa[e];
                acc[k] = fmaf(iy, q.y, acc[k] + q.x);
            }
        }
    }

    const float scale = (float)(M_PI / 360.0);   // pi / (2*L)
    float* po = out + ((size_t)(n * W + i0t + wid) * W) + j;
#pragma unroll
    for (int k = 0; k < 4; k++) {
        po[(size_t)(8 * k) * W] = acc[k] * scale;
    }
}

// ---------------------------------------------------------------------------
extern "C" void kernel_launch(void* const* d_in, const int* in_sizes, int n_in,
                              void* d_out, int out_size) {
    const float* x = (const float*)d_in[0];
    float* out = (float*)d_out;
    (void)in_sizes; (void)n_in; (void)out_size;

    irad_prep<<<dim3(L, NB), 128>>>(x);
    irad_main<<<dim3(W / TJ, W / TI, NB), 256>>>(out);
}